// round 3
// baseline (speedup 1.0000x reference)
#include <cuda_runtime.h>
#include <cuda_bf16.h>
#include <cstddef>

// Dims:
// x  : 131072 floats                  = (2048 ij, 64 m)
// Ci : 4194304 floats (512,4,512,4)   = (2048 ij, 2048 kl), values exactly {0,1}
// Wi : 33554432 floats (512,4,4,64,64)-> flat b*16384 + k*4096 + l*64 + m, b=i*4+j
// y  : 131072 floats (512,4,64)       -> b*64 + l
//
// xr[kl, m] = sum_ij Ci[ij,kl] * x[ij,m]   (Ci binary -> conditional add)
// y[b, l]   = sum_{k,m} Wi[b,k,l,m] * xr[(b>>2)*256 + k*64 + m]

#define N_IJ   2048
#define N_KL   2048
#define N_M    64
#define KLB    64      // kl per route block
#define IJC    512     // ij per route block (chunk)
#define NCHUNK 4       // 2048 / 512
#define XR_N   131072  // 2048*64

// 4 partial groups + final xr
__device__ float g_part[NCHUNK * XR_N];   // 2 MB
__device__ float g_xr[XR_N];              // 512 KB

// Route smem: sx (512*64 floats = 128 KB) + sCib bytes (512*65 = 33280 B)
#define SMEM_SX_FLOATS   (IJC * N_M)
#define SMEM_CI_PAD      65
#define SMEM_ROUTE_BYTES (SMEM_SX_FLOATS * 4 + IJC * SMEM_CI_PAD)

// ---------------------------------------------------------------------------
// Kernel 1: routing. grid = 32 kl-groups * 4 ij-chunks = 128 blocks, 256 thr.
// Warp w owns kl_local = w*8 .. w*8+7 (warp-uniform kl -> no divergence).
// For each kl: ballot-scan 512 ij in 32-wide steps; each set bit is one add
// of the x row (lanes cover m as float2). Ci==1 exactly, so no multiply.
// ---------------------------------------------------------------------------
__global__ void __launch_bounds__(256) route_kernel(const float* __restrict__ Ci,
                                                    const float* __restrict__ x)
{
    extern __shared__ unsigned char dynsmem[];
    float* sx = reinterpret_cast<float*>(dynsmem);                 // [512][64]
    unsigned char* sCib = dynsmem + SMEM_SX_FLOATS * 4;            // [512][65]

    const int bx    = blockIdx.x;
    const int klg   = bx >> 2;          // 0..31
    const int chunk = bx & 3;           // 0..3
    const int t     = threadIdx.x;
    const int w     = t >> 5;
    const int lane  = t & 31;

    const int kl0 = klg * KLB;
    const int ij0 = chunk * IJC;

    // Stage x chunk: 512*64 floats contiguous (128 KB), float4 coalesced
    {
        const float4* xg = reinterpret_cast<const float4*>(x + ij0 * N_M);
        float4* sx4 = reinterpret_cast<float4*>(sx);
        #pragma unroll
        for (int p = 0; p < 32; p++)
            sx4[p * 256 + t] = xg[p * 256 + t];
    }
    // Stage Ci tile as bytes: [512 ij][64 kl] -> sCib[ij*65 + kl]
    {
        #pragma unroll
        for (int p = 0; p < 32; p++) {
            int idx = p * 1024 + t * 4;      // float index in 512x64 tile
            int r = idx >> 6, c = idx & 63;
            float4 v = *reinterpret_cast<const float4*>(
                Ci + (size_t)(ij0 + r) * N_KL + kl0 + c);
            unsigned char* dst = sCib + r * SMEM_CI_PAD + c;
            dst[0] = (v.x != 0.0f);
            dst[1] = (v.y != 0.0f);
            dst[2] = (v.z != 0.0f);
            dst[3] = (v.w != 0.0f);
        }
    }
    __syncthreads();

    // Scan: warp-uniform kl, ballot over 32 ij at a time
    #pragma unroll 1
    for (int klw = 0; klw < 8; klw++) {
        const int kl_local = w * 8 + klw;
        float2 acc = make_float2(0.f, 0.f);

        unsigned char c = sCib[lane * SMEM_CI_PAD + kl_local];
        #pragma unroll 1
        for (int ijs = 0; ijs < IJC; ijs += 32) {
            // prefetch next step's byte to hide LDS latency under the pops
            unsigned char cn = (ijs + 32 < IJC)
                ? sCib[(ijs + 32 + lane) * SMEM_CI_PAD + kl_local] : (unsigned char)0;
            unsigned mask = __ballot_sync(0xFFFFFFFFu, c != 0);
            while (mask) {
                int bidx = __ffs(mask) - 1;
                mask &= mask - 1;
                const float2 v = *reinterpret_cast<const float2*>(
                    sx + (ijs + bidx) * N_M + lane * 2);
                acc.x += v.x;
                acc.y += v.y;
            }
            c = cn;
        }
        // coalesced float2 store of this kl's partial row
        *reinterpret_cast<float2*>(
            &g_part[(size_t)chunk * XR_N + (size_t)(kl0 + kl_local) * N_M + lane * 2]) = acc;
    }
}

// ---------------------------------------------------------------------------
// Kernel 2: fold 4 partials -> xr (L2-hot, ~2.5 MB traffic)
// ---------------------------------------------------------------------------
__global__ void __launch_bounds__(256) reduce_kernel()
{
    int t = blockIdx.x * 256 + threadIdx.x;
    g_xr[t] = g_part[t] + g_part[XR_N + t] + g_part[2 * XR_N + t] + g_part[3 * XR_N + t];
}

// ---------------------------------------------------------------------------
// Kernel 3: per-capsule transform. grid = 2048 (b), 256 thr.
// Warp w -> l = w*8..w*8+7. Lane L: ka = L>>4 in {0,1}, mi = L&15 (float4 m).
// All 16 Wi float4 loads issued up front (max MLP), xr from smem, partial
// per (l, lane) reduced through padded smem (no shuffles).
// ---------------------------------------------------------------------------
__global__ void __launch_bounds__(256) transform_kernel(const float* __restrict__ Wi,
                                                        float* __restrict__ y)
{
    __shared__ float sxr[256];
    __shared__ float part[64 * 33];

    const int b = blockIdx.x;
    const int i = b >> 2;
    const int t = threadIdx.x;
    const int w = t >> 5;
    const int L = t & 31;
    const int ka = L >> 4;
    const int mi = L & 15;

    const float4* W4 = reinterpret_cast<const float4*>(Wi + (size_t)b * 16384);

    // Front-load all 16 Wi vectors (independent of xr -> overlap with staging)
    float4 wv[8][2];
    #pragma unroll
    for (int q = 0; q < 8; q++) {
        const int l = w * 8 + q;
        #pragma unroll
        for (int kk = 0; kk < 2; kk++) {
            const int k = ka + 2 * kk;
            wv[q][kk] = W4[k * 1024 + l * 16 + mi];
        }
    }

    sxr[t] = g_xr[i * 256 + t];
    __syncthreads();

    const float4* sxr4 = reinterpret_cast<const float4*>(sxr);
    float4 xv0 = sxr4[ka * 16 + mi];
    float4 xv1 = sxr4[(ka + 2) * 16 + mi];

    #pragma unroll
    for (int q = 0; q < 8; q++) {
        float4 a = wv[q][0];
        float4 c = wv[q][1];
        float acc;
        acc  = a.x * xv0.x;
        acc  = fmaf(a.y, xv0.y, acc);
        acc  = fmaf(a.z, xv0.z, acc);
        acc  = fmaf(a.w, xv0.w, acc);
        acc  = fmaf(c.x, xv1.x, acc);
        acc  = fmaf(c.y, xv1.y, acc);
        acc  = fmaf(c.z, xv1.z, acc);
        acc  = fmaf(c.w, xv1.w, acc);
        part[(w * 8 + q) * 33 + L] = acc;
    }
    __syncthreads();

    if (t < 64) {
        float s = 0.f;
        #pragma unroll
        for (int j = 0; j < 32; j++)
            s += part[t * 33 + j];
        y[b * 64 + t] = s;
    }
}

// ---------------------------------------------------------------------------
extern "C" void kernel_launch(void* const* d_in, const int* in_sizes, int n_in,
                              void* d_out, int out_size)
{
    const float* x  = nullptr;
    const float* Ci = nullptr;
    const float* Wi = nullptr;
    for (int i = 0; i < n_in; i++) {
        if (in_sizes[i] == 131072)        x  = (const float*)d_in[i];
        else if (in_sizes[i] == 4194304)  Ci = (const float*)d_in[i];
        else if (in_sizes[i] == 33554432) Wi = (const float*)d_in[i];
    }
    float* y = (float*)d_out;

    cudaFuncSetAttribute(route_kernel,
                         cudaFuncAttributeMaxDynamicSharedMemorySize,
                         SMEM_ROUTE_BYTES);

    route_kernel<<<128, 256, SMEM_ROUTE_BYTES>>>(Ci, x);
    reduce_kernel<<<512, 256>>>();
    transform_kernel<<<2048, 256>>>(Wi, y);
}

// round 5
// speedup vs baseline: 1.5766x; 1.5766x over previous
#include <cuda_runtime.h>
#include <cuda_bf16.h>
#include <cstddef>

// Dims:
// x  : 131072 floats                  = (2048 ij, 64 m)
// Ci : 4194304 floats (512,4,512,4)   = (2048 ij, 2048 kl), values exactly {0,1}
// Wi : 33554432 floats (512,4,4,64,64)-> flat b*16384 + k*4096 + l*64 + m, b=i*4+j
// y  : 131072 floats (512,4,64)       -> b*64 + l
//
// xr[kl, m] = sum_ij Ci[ij,kl] * x[ij,m]   (Ci binary -> conditional add)
// y[b, l]   = sum_{k,m} Wi[b,k,l,m] * xr[(b>>2)*256 + k*64 + m]

#define N_KL   2048
#define N_M    64
#define IJT    128     // ij per route block (tile)
#define KLB    64      // kl per route block
#define NCHUNK 16      // 2048 / 128
#define NKLG   32      // 2048 / 64
#define XR_N   131072  // 2048*64
#define CI_PAD 65

__device__ float g_part[NCHUNK * XR_N];   // 8 MB partials
__device__ float g_xr[XR_N];              // 512 KB reduced

// ---------------------------------------------------------------------------
// Kernel 1: routing. grid = 512 (klg = bx&31 fastest, chunk = bx>>5).
// Block: 256 thr = 8 warps; warp w owns kl_local = w*8+q, q=0..7 (warp-uniform
// kl). Per 32-ij word: one LDS byte + one ballot -> uniform mask; pop bits
// uniformly (no divergence). x tile 32 KB + Ci byte tile 8.3 KB static smem.
// ---------------------------------------------------------------------------
__global__ void __launch_bounds__(256) route_kernel(const float* __restrict__ Ci,
                                                    const float* __restrict__ x)
{
    __shared__ float sx[IJT * N_M];               // 32 KB
    __shared__ unsigned char sCib[IJT * CI_PAD];  // 8.3 KB

    const int bx    = blockIdx.x;
    const int klg   = bx & 31;
    const int chunk = bx >> 5;
    const int t     = threadIdx.x;
    const int w     = t >> 5;
    const int lane  = t & 31;

    const int kl0 = klg * KLB;
    const int ij0 = chunk * IJT;

    // Stage x tile: 128 ij x 64 m, contiguous (2048 float4)
    {
        const float4* xg = reinterpret_cast<const float4*>(x + ij0 * N_M);
        float4* sx4 = reinterpret_cast<float4*>(sx);
        #pragma unroll
        for (int p = 0; p < 8; p++)
            sx4[p * 256 + t] = xg[p * 256 + t];
    }
    // Stage Ci tile as bytes: [128 ij][64 kl] -> sCib[r*65 + c]
    {
        #pragma unroll
        for (int p = 0; p < 8; p++) {
            int f = p * 256 + t;          // float4 id in 128x16 grid
            int r = f >> 4, c4 = (f & 15) * 4;
            float4 v = *reinterpret_cast<const float4*>(
                Ci + (size_t)(ij0 + r) * N_KL + kl0 + c4);
            unsigned char* dst = sCib + r * CI_PAD + c4;
            dst[0] = (v.x != 0.0f);
            dst[1] = (v.y != 0.0f);
            dst[2] = (v.z != 0.0f);
            dst[3] = (v.w != 0.0f);
        }
    }
    __syncthreads();

    // Scan: warp-uniform kl; ballot builds a uniform mask per 32 ij
    #pragma unroll 1
    for (int q = 0; q < 8; q++) {
        const int kl_local = w * 8 + q;
        float2 acc = make_float2(0.f, 0.f);

        #pragma unroll
        for (int ww = 0; ww < 4; ww++) {
            unsigned char cb = sCib[(ww * 32 + lane) * CI_PAD + kl_local];
            unsigned mask = __ballot_sync(0xFFFFFFFFu, cb != 0);
            while (mask) {
                int bidx = __ffs(mask) - 1;
                mask &= mask - 1;
                const float2 v = *reinterpret_cast<const float2*>(
                    sx + (ww * 32 + bidx) * N_M + lane * 2);
                acc.x += v.x;
                acc.y += v.y;
            }
        }
        *reinterpret_cast<float2*>(
            &g_part[(size_t)chunk * XR_N + (size_t)(kl0 + kl_local) * N_M + lane * 2]) = acc;
    }
}

// ---------------------------------------------------------------------------
// Kernel 2: fold 16 partials -> xr (8.5 MB L2 traffic)
// ---------------------------------------------------------------------------
__global__ void __launch_bounds__(256) reduce_kernel()
{
    int t = blockIdx.x * 256 + threadIdx.x;
    float s = 0.f;
    #pragma unroll
    for (int g = 0; g < NCHUNK; g++)
        s += g_part[(size_t)g * XR_N + t];
    g_xr[t] = s;
}

// ---------------------------------------------------------------------------
// Kernel 3: per-capsule transform. grid = 2048 (b), 256 thr.
// Warp w -> l = w*8 .. w*8+7. Lane L: ka = L>>4 in {0,1}, mi = L&15.
// Two passes of 8 front-batched __ldcs float4 loads (regs ~52 -> 4 blk/SM),
// padded-smem reduction. Wi streamed once (128 MB) -> HBM-bound.
// ---------------------------------------------------------------------------
__global__ void __launch_bounds__(256) transform_kernel(const float* __restrict__ Wi,
                                                        float* __restrict__ y)
{
    __shared__ float sxr[256];
    __shared__ float part[64 * 33];

    const int b = blockIdx.x;
    const int i = b >> 2;
    const int t = threadIdx.x;
    const int w = t >> 5;
    const int L = t & 31;
    const int ka = L >> 4;
    const int mi = L & 15;

    const float4* W4 = reinterpret_cast<const float4*>(Wi + (size_t)b * 16384);

    // Pass-0 weight loads issued before the barrier (independent of xr)
    float4 wv[4][2];
    #pragma unroll
    for (int qq = 0; qq < 4; qq++) {
        const int l = w * 8 + qq;
        wv[qq][0] = __ldcs(&W4[ka * 1024 + l * 16 + mi]);
        wv[qq][1] = __ldcs(&W4[(ka + 2) * 1024 + l * 16 + mi]);
    }

    sxr[t] = g_xr[i * 256 + t];
    __syncthreads();

    const float4* sxr4 = reinterpret_cast<const float4*>(sxr);
    const float4 xv0 = sxr4[ka * 16 + mi];
    const float4 xv1 = sxr4[(ka + 2) * 16 + mi];

    #pragma unroll
    for (int h = 0; h < 2; h++) {
        if (h == 1) {
            #pragma unroll
            for (int qq = 0; qq < 4; qq++) {
                const int l = w * 8 + 4 + qq;
                wv[qq][0] = __ldcs(&W4[ka * 1024 + l * 16 + mi]);
                wv[qq][1] = __ldcs(&W4[(ka + 2) * 1024 + l * 16 + mi]);
            }
        }
        #pragma unroll
        for (int qq = 0; qq < 4; qq++) {
            float4 a = wv[qq][0];
            float4 c = wv[qq][1];
            float acc;
            acc = a.x * xv0.x;
            acc = fmaf(a.y, xv0.y, acc);
            acc = fmaf(a.z, xv0.z, acc);
            acc = fmaf(a.w, xv0.w, acc);
            acc = fmaf(c.x, xv1.x, acc);
            acc = fmaf(c.y, xv1.y, acc);
            acc = fmaf(c.z, xv1.z, acc);
            acc = fmaf(c.w, xv1.w, acc);
            part[(w * 8 + h * 4 + qq) * 33 + L] = acc;
        }
    }
    __syncthreads();

    if (t < 64) {
        float s = 0.f;
        #pragma unroll
        for (int j = 0; j < 32; j++)
            s += part[t * 33 + j];
        y[b * 64 + t] = s;
    }
}

// ---------------------------------------------------------------------------
extern "C" void kernel_launch(void* const* d_in, const int* in_sizes, int n_in,
                              void* d_out, int out_size)
{
    const float* x  = nullptr;
    const float* Ci = nullptr;
    const float* Wi = nullptr;
    for (int i = 0; i < n_in; i++) {
        if (in_sizes[i] == 131072)        x  = (const float*)d_in[i];
        else if (in_sizes[i] == 4194304)  Ci = (const float*)d_in[i];
        else if (in_sizes[i] == 33554432) Wi = (const float*)d_in[i];
    }
    float* y = (float*)d_out;

    route_kernel<<<NKLG * NCHUNK, 256>>>(Ci, x);
    reduce_kernel<<<XR_N / 256, 256>>>();
    transform_kernel<<<2048, 256>>>(Wi, y);
}

// round 6
// speedup vs baseline: 1.5894x; 1.0081x over previous
#include <cuda_runtime.h>
#include <cuda_bf16.h>
#include <cstddef>

// Dims:
// x  : 131072 floats                  = (2048 ij, 64 m)
// Ci : 4194304 floats (512,4,512,4)   = (2048 ij, 2048 kl), values exactly {0,1}
// Wi : 33554432 floats (512,4,4,64,64)-> flat b*16384 + k*4096 + l*64 + m, b=i*4+j
// y  : 131072 floats (512,4,64)       -> b*64 + l
//
// xr[kl, m] = sum_ij Ci[ij,kl] * x[ij,m]   (Ci binary -> conditional add)
// y[b, l]   = sum_{k,m} Wi[b,k,l,m] * xr[(b>>2)*256 + k*64 + m]

#define N_KL   2048
#define N_M    64
#define IJT    64      // ij per route block
#define KLB    64      // kl per route block
#define NCHUNK 32      // 2048 / 64
#define NKLG   32      // 2048 / 64
#define XR_N   131072  // 2048*64
#define CI_PAD 65

__device__ float g_part[NCHUNK * XR_N];   // 16 MB partials (L2-resident)
__device__ float g_xr[XR_N];              // 512 KB reduced

// ---------------------------------------------------------------------------
// Kernel 1: routing. grid = 1024 (klg = bx&31 fastest for x L2-reuse,
// chunk = bx>>5). 256 thr / 8 warps; warp w owns kl_local = w*8+q.
// Phase A: stage x (16 KB) + Ci bytes (4.2 KB). Phase B: 128 threads build
// 128 ij-bitmasks (64 kl x 2 groups) with independent byte-LDS (MLP).
// Phase C: scan — per kl read 2 mask words, dual-pop with 2 acc chains.
// ---------------------------------------------------------------------------
__global__ void __launch_bounds__(256) route_kernel(const float* __restrict__ Ci,
                                                    const float* __restrict__ x)
{
    __shared__ float sx[IJT * N_M];               // 16 KB
    __shared__ unsigned char sCib[IJT * CI_PAD];  // 4.2 KB
    __shared__ unsigned smask[2 * KLB];           // 512 B  [group][kl]

    const int bx    = blockIdx.x;
    const int klg   = bx & 31;
    const int chunk = bx >> 5;
    const int t     = threadIdx.x;
    const int w     = t >> 5;
    const int lane  = t & 31;

    const int kl0 = klg * KLB;
    const int ij0 = chunk * IJT;

    // Stage x tile: 64 ij x 64 m contiguous (1024 float4)
    {
        const float4* xg = reinterpret_cast<const float4*>(x + ij0 * N_M);
        float4* sx4 = reinterpret_cast<float4*>(sx);
        #pragma unroll
        for (int p = 0; p < 4; p++)
            sx4[p * 256 + t] = xg[p * 256 + t];
    }
    // Stage Ci tile as bytes: [64 ij][64 kl] -> sCib[r*65 + c]
    {
        #pragma unroll
        for (int p = 0; p < 4; p++) {
            int f = p * 256 + t;          // float4 id in 64x16 grid
            int r = f >> 4, c4 = (f & 15) * 4;
            float4 v = *reinterpret_cast<const float4*>(
                Ci + (size_t)(ij0 + r) * N_KL + kl0 + c4);
            unsigned char* dst = sCib + r * CI_PAD + c4;
            dst[0] = (v.x != 0.0f);
            dst[1] = (v.y != 0.0f);
            dst[2] = (v.z != 0.0f);
            dst[3] = (v.w != 0.0f);
        }
    }
    __syncthreads();

    // Build bitmasks: thread t<128 -> g = t>>6, klc = t&63.
    // 32 independent byte loads, fully unrolled -> latency overlapped.
    if (t < 128) {
        const int g   = t >> 6;
        const int klc = t & 63;
        const unsigned char* col = sCib + g * 32 * CI_PAD + klc;
        unsigned m = 0u;
        #pragma unroll
        for (int i = 0; i < 32; i++)
            m |= (unsigned)(col[i * CI_PAD] != 0) << i;
        smask[t] = m;
    }
    __syncthreads();

    // Scan: warp-uniform kl, dual-pop, two accumulator chains
    const int lane2 = lane * 2;
    #pragma unroll 1
    for (int q = 0; q < 8; q++) {
        const int klc = w * 8 + q;
        float2 a0 = make_float2(0.f, 0.f);
        float2 a1 = make_float2(0.f, 0.f);

        #pragma unroll
        for (int g = 0; g < 2; g++) {
            unsigned mask = smask[g * KLB + klc];
            const float* base = sx + g * 32 * N_M + lane2;
            while (mask) {
                int b0 = __ffs(mask) - 1; mask &= mask - 1;
                float2 v0 = *reinterpret_cast<const float2*>(base + b0 * N_M);
                if (mask) {
                    int b1 = __ffs(mask) - 1; mask &= mask - 1;
                    float2 v1 = *reinterpret_cast<const float2*>(base + b1 * N_M);
                    a1.x += v1.x; a1.y += v1.y;
                }
                a0.x += v0.x; a0.y += v0.y;
            }
        }
        float2 out = make_float2(a0.x + a1.x, a0.y + a1.y);
        *reinterpret_cast<float2*>(
            &g_part[(size_t)chunk * XR_N + (size_t)(kl0 + klc) * N_M + lane2]) = out;
    }
}

// ---------------------------------------------------------------------------
// Kernel 2: fold 32 partials -> xr (~16.5 MB L2 traffic)
// ---------------------------------------------------------------------------
__global__ void __launch_bounds__(256) reduce_kernel()
{
    int t = blockIdx.x * 256 + threadIdx.x;
    float s0 = 0.f, s1 = 0.f;
    #pragma unroll
    for (int g = 0; g < NCHUNK; g += 2) {
        s0 += g_part[(size_t)g * XR_N + t];
        s1 += g_part[(size_t)(g + 1) * XR_N + t];
    }
    g_xr[t] = s0 + s1;
}

// ---------------------------------------------------------------------------
// Kernel 3: per-capsule transform. grid = 4096: b = bx>>1, half = bx&1
// (32 l-values per block). Warp w -> l = half*32 + w*4 + qq, qq=0..3.
// Lane L: ka = L>>4 in {0,1}, mi = L&15. 8 front-batched __ldcs float4 per
// thread (max MLP, Wi streamed once = 128 MB), padded-smem reduction.
// ---------------------------------------------------------------------------
__global__ void __launch_bounds__(256) transform_kernel(const float* __restrict__ Wi,
                                                        float* __restrict__ y)
{
    __shared__ float sxr[256];
    __shared__ float part[32 * 33];

    const int bx   = blockIdx.x;
    const int b    = bx >> 1;
    const int half = bx & 1;
    const int i    = b >> 2;
    const int t    = threadIdx.x;
    const int w    = t >> 5;
    const int L    = t & 31;
    const int ka   = L >> 4;
    const int mi   = L & 15;

    const float4* W4 = reinterpret_cast<const float4*>(Wi + (size_t)b * 16384);
    const int l_base = half * 32 + w * 4;

    // Front-load all 8 weight vectors (independent of xr -> overlap staging)
    float4 wv[4][2];
    #pragma unroll
    for (int qq = 0; qq < 4; qq++) {
        const int l = l_base + qq;
        wv[qq][0] = __ldcs(&W4[ka * 1024 + l * 16 + mi]);
        wv[qq][1] = __ldcs(&W4[(ka + 2) * 1024 + l * 16 + mi]);
    }

    sxr[t] = g_xr[i * 256 + t];
    __syncthreads();

    const float4* sxr4 = reinterpret_cast<const float4*>(sxr);
    const float4 xv0 = sxr4[ka * 16 + mi];
    const float4 xv1 = sxr4[(ka + 2) * 16 + mi];

    #pragma unroll
    for (int qq = 0; qq < 4; qq++) {
        float4 a = wv[qq][0];
        float4 c = wv[qq][1];
        float acc;
        acc = a.x * xv0.x;
        acc = fmaf(a.y, xv0.y, acc);
        acc = fmaf(a.z, xv0.z, acc);
        acc = fmaf(a.w, xv0.w, acc);
        acc = fmaf(c.x, xv1.x, acc);
        acc = fmaf(c.y, xv1.y, acc);
        acc = fmaf(c.z, xv1.z, acc);
        acc = fmaf(c.w, xv1.w, acc);
        part[(w * 4 + qq) * 33 + L] = acc;
    }
    __syncthreads();

    if (t < 32) {
        float s = 0.f;
        #pragma unroll
        for (int j = 0; j < 32; j++)
            s += part[t * 33 + j];
        y[b * 64 + half * 32 + t] = s;
    }
}

// ---------------------------------------------------------------------------
extern "C" void kernel_launch(void* const* d_in, const int* in_sizes, int n_in,
                              void* d_out, int out_size)
{
    const float* x  = nullptr;
    const float* Ci = nullptr;
    const float* Wi = nullptr;
    for (int i = 0; i < n_in; i++) {
        if (in_sizes[i] == 131072)        x  = (const float*)d_in[i];
        else if (in_sizes[i] == 4194304)  Ci = (const float*)d_in[i];
        else if (in_sizes[i] == 33554432) Wi = (const float*)d_in[i];
    }
    float* y = (float*)d_out;

    route_kernel<<<NKLG * NCHUNK, 256>>>(Ci, x);
    reduce_kernel<<<XR_N / 256, 256>>>();
    transform_kernel<<<4096, 256>>>(Wi, y);
}

// round 8
// speedup vs baseline: 1.6624x; 1.0459x over previous
#include <cuda_runtime.h>
#include <cuda_bf16.h>
#include <cstddef>

// Dims:
// x  : 131072 floats                  = (2048 ij, 64 m)
// Ci : 4194304 floats (512,4,512,4)   = (2048 ij, 2048 kl), values exactly {0,1}
// Wi : 33554432 floats (512,4,4,64,64)-> flat b*16384 + k*4096 + l*64 + m, b=i*4+j
// y  : 131072 floats (512,4,64)       -> b*64 + l
//
// xr[kl, m] = sum_ij Ci[ij,kl] * x[ij,m]   (Ci binary -> conditional add)
// y[b, l]   = sum_{k,m} Wi[b,k,l,m] * xr[(b>>2)*256 + k*64 + m]

#define N_KL   2048
#define N_M    64
#define IJT    64      // ij per route block
#define KLB    64      // kl per route block
#define NCHUNK 32      // 2048 / 64
#define NKLG   32      // 2048 / 64
#define XR_N   131072  // 2048*64
#define CI_PAD 65

__device__ float g_part[NCHUNK * XR_N];   // 16 MB partials (L2-resident)
__device__ float g_xr[XR_N];              // 512 KB reduced

// ---------------------------------------------------------------------------
// Kernel 1: routing. grid = 1024 (klg fastest for x L2-reuse).
// Phase A: stage x (16 KB) + Ci bytes. Phase B: build 128 ij-bitmasks.
// Phase C: scan — per kl: 2 mask words, SINGLE-pop while loop (no inner if,
// no per-iteration reconvergence), packed add.rn.f32x2 accumulate.
// ---------------------------------------------------------------------------
__global__ void __launch_bounds__(256) route_kernel(const float* __restrict__ Ci,
                                                    const float* __restrict__ x)
{
    __shared__ float sx[IJT * N_M];               // 16 KB
    __shared__ unsigned char sCib[IJT * CI_PAD];  // 4.2 KB
    __shared__ unsigned smask[2 * KLB];           // 512 B  [group][kl]

    const int bx    = blockIdx.x;
    const int klg   = bx & 31;
    const int chunk = bx >> 5;
    const int t     = threadIdx.x;
    const int w     = t >> 5;
    const int lane  = t & 31;

    const int kl0 = klg * KLB;
    const int ij0 = chunk * IJT;

    // Stage x tile: 64 ij x 64 m contiguous (1024 float4)
    {
        const float4* xg = reinterpret_cast<const float4*>(x + ij0 * N_M);
        float4* sx4 = reinterpret_cast<float4*>(sx);
        #pragma unroll
        for (int p = 0; p < 4; p++)
            sx4[p * 256 + t] = xg[p * 256 + t];
    }
    // Stage Ci tile as bytes: [64 ij][64 kl] -> sCib[r*65 + c]
    {
        #pragma unroll
        for (int p = 0; p < 4; p++) {
            int f = p * 256 + t;          // float4 id in 64x16 grid
            int r = f >> 4, c4 = (f & 15) * 4;
            float4 v = *reinterpret_cast<const float4*>(
                Ci + (size_t)(ij0 + r) * N_KL + kl0 + c4);
            unsigned char* dst = sCib + r * CI_PAD + c4;
            dst[0] = (v.x != 0.0f);
            dst[1] = (v.y != 0.0f);
            dst[2] = (v.z != 0.0f);
            dst[3] = (v.w != 0.0f);
        }
    }
    __syncthreads();

    // Build bitmasks: thread t<128 -> g = t>>6, klc = t&63.
    if (t < 128) {
        const int g   = t >> 6;
        const int klc = t & 63;
        const unsigned char* col = sCib + g * 32 * CI_PAD + klc;
        unsigned m = 0u;
        #pragma unroll
        for (int i = 0; i < 32; i++)
            m |= (unsigned)(col[i * CI_PAD] != 0) << i;
        smask[t] = m;
    }
    __syncthreads();

    // Scan: warp-uniform kl; flat single-pop loop, packed f32x2 accumulate.
    const int lane2 = lane * 2;
    #pragma unroll 1
    for (int q = 0; q < 8; q++) {
        const int klc = w * 8 + q;
        unsigned long long acc = 0ull;   // two packed fp32 zeros

        #pragma unroll
        for (int g = 0; g < 2; g++) {
            unsigned mask = smask[g * KLB + klc];
            const float* base = sx + g * 32 * N_M + lane2;
            while (mask) {
                int b0 = __ffs(mask) - 1;
                mask &= mask - 1;
                unsigned long long v =
                    *reinterpret_cast<const unsigned long long*>(base + b0 * N_M);
                asm("add.rn.f32x2 %0, %0, %1;" : "+l"(acc) : "l"(v));
            }
        }
        float2 out;
        asm("mov.b64 {%0, %1}, %2;" : "=f"(out.x), "=f"(out.y) : "l"(acc));
        *reinterpret_cast<float2*>(
            &g_part[(size_t)chunk * XR_N + (size_t)(kl0 + klc) * N_M + lane2]) = out;
    }
}

// ---------------------------------------------------------------------------
// Kernel 2: fold 32 partials -> xr (~16.5 MB L2 traffic)
// ---------------------------------------------------------------------------
__global__ void __launch_bounds__(256) reduce_kernel()
{
    int t = blockIdx.x * 256 + threadIdx.x;
    float s0 = 0.f, s1 = 0.f;
    #pragma unroll
    for (int g = 0; g < NCHUNK; g += 2) {
        s0 += g_part[(size_t)g * XR_N + t];
        s1 += g_part[(size_t)(g + 1) * XR_N + t];
    }
    g_xr[t] = s0 + s1;
}

// ---------------------------------------------------------------------------
// Kernel 3: per-capsule transform. grid = 4096: b = bx>>1, half = bx&1.
// Warp w -> l = half*32 + w*4 + qq. Lane L: ka = L>>4, mi = L&15.
// 8 front-batched __ldcs float4 per thread, padded-smem reduction.
// Wi streamed once (128 MB) -> HBM-bound.
// ---------------------------------------------------------------------------
__global__ void __launch_bounds__(256) transform_kernel(const float* __restrict__ Wi,
                                                        float* __restrict__ y)
{
    __shared__ float sxr[256];
    __shared__ float part[32 * 33];

    const int bx   = blockIdx.x;
    const int b    = bx >> 1;
    const int half = bx & 1;
    const int i    = b >> 2;
    const int t    = threadIdx.x;
    const int w    = t >> 5;
    const int L    = t & 31;
    const int ka   = L >> 4;
    const int mi   = L & 15;

    const float4* W4 = reinterpret_cast<const float4*>(Wi + (size_t)b * 16384);
    const int l_base = half * 32 + w * 4;

    // Front-load all 8 weight vectors (independent of xr -> overlap staging)
    float4 wv[4][2];
    #pragma unroll
    for (int qq = 0; qq < 4; qq++) {
        const int l = l_base + qq;
        wv[qq][0] = __ldcs(&W4[ka * 1024 + l * 16 + mi]);
        wv[qq][1] = __ldcs(&W4[(ka + 2) * 1024 + l * 16 + mi]);
    }

    sxr[t] = g_xr[i * 256 + t];
    __syncthreads();

    const float4* sxr4 = reinterpret_cast<const float4*>(sxr);
    const float4 xv0 = sxr4[ka * 16 + mi];
    const float4 xv1 = sxr4[(ka + 2) * 16 + mi];

    #pragma unroll
    for (int qq = 0; qq < 4; qq++) {
        float4 a = wv[qq][0];
        float4 c = wv[qq][1];
        float acc;
        acc = a.x * xv0.x;
        acc = fmaf(a.y, xv0.y, acc);
        acc = fmaf(a.z, xv0.z, acc);
        acc = fmaf(a.w, xv0.w, acc);
        acc = fmaf(c.x, xv1.x, acc);
        acc = fmaf(c.y, xv1.y, acc);
        acc = fmaf(c.z, xv1.z, acc);
        acc = fmaf(c.w, xv1.w, acc);
        part[(w * 4 + qq) * 33 + L] = acc;
    }
    __syncthreads();

    if (t < 32) {
        float s = 0.f;
        #pragma unroll
        for (int j = 0; j < 32; j++)
            s += part[t * 33 + j];
        y[b * 64 + half * 32 + t] = s;
    }
}

// ---------------------------------------------------------------------------
extern "C" void kernel_launch(void* const* d_in, const int* in_sizes, int n_in,
                              void* d_out, int out_size)
{
    const float* x  = nullptr;
    const float* Ci = nullptr;
    const float* Wi = nullptr;
    for (int i = 0; i < n_in; i++) {
        if (in_sizes[i] == 131072)        x  = (const float*)d_in[i];
        else if (in_sizes[i] == 4194304)  Ci = (const float*)d_in[i];
        else if (in_sizes[i] == 33554432) Wi = (const float*)d_in[i];
    }
    float* y = (float*)d_out;

    route_kernel<<<NKLG * NCHUNK, 256>>>(Ci, x);
    reduce_kernel<<<XR_N / 256, 256>>>();
    transform_kernel<<<4096, 256>>>(Wi, y);
}

// round 9
// speedup vs baseline: 1.8816x; 1.1319x over previous
#include <cuda_runtime.h>
#include <cuda_bf16.h>
#include <cstdint>
#include <cstddef>

// Dims:
// x  : 131072 floats                  = (2048 ij, 64 m)
// Ci : 4194304 floats (512,4,512,4)   = (2048 ij, 2048 kl), values exactly {0,1}
// Wi : 33554432 floats (512,4,4,64,64)-> flat b*16384 + k*4096 + l*64 + m, b=i*4+j
// y  : 131072 floats (512,4,64)       -> b*64 + l
//
// xr[kl, m] = sum_ij Ci[ij,kl] * x[ij,m]
// y[b, l]   = sum_{k,m} Wi[b,k,l,m] * xr[(b>>2)*256 + k*64 + m]

#define N_KL   2048
#define N_M    64
#define XR_N   131072
#define NCHUNK 8       // ij splits (256 ij each)
#define NKLT   32      // kl tiles (64 kl each)
#define IJB    256

__device__ float g_part[NCHUNK * XR_N];   // 4 MB partials
__device__ float g_xr[XR_N];              // 512 KB

// Route dynamic smem layout: 3 tiles of 256 rows x 128 bytes, SW128-swizzled
#define SM_A   0        // Ci bf16 [256 ij][64 kl]
#define SM_XH  32768    // x hi bf16 [256 ij][64 m]
#define SM_XL  65536    // x lo bf16 [256 ij][64 m]
#define SMEM_ROUTE 98304

__device__ __forceinline__ uint32_t swz(uint32_t off) {
    return off ^ ((off >> 3) & 0x70);
}

__device__ __forceinline__ void ldsm4t(uint32_t& r0, uint32_t& r1,
                                       uint32_t& r2, uint32_t& r3, uint32_t addr) {
    asm volatile("ldmatrix.sync.aligned.m8n8.x4.trans.shared.b16 {%0,%1,%2,%3}, [%4];"
                 : "=r"(r0), "=r"(r1), "=r"(r2), "=r"(r3) : "r"(addr));
}

__device__ __forceinline__ void mma16816(float* c, uint32_t a0, uint32_t a1,
                                         uint32_t a2, uint32_t a3,
                                         uint32_t b0, uint32_t b1) {
    asm volatile("mma.sync.aligned.m16n8k16.row.col.f32.bf16.bf16.f32 "
                 "{%0,%1,%2,%3}, {%4,%5,%6,%7}, {%8,%9}, {%0,%1,%2,%3};"
                 : "+f"(c[0]), "+f"(c[1]), "+f"(c[2]), "+f"(c[3])
                 : "r"(a0), "r"(a1), "r"(a2), "r"(a3), "r"(b0), "r"(b1));
}

// ---------------------------------------------------------------------------
// Kernel 1: routing via bf16 tensor cores, fp32 accuracy by hi/lo split.
// grid = 256: klt = bx&31 (fastest, x L2-reuse), chunk = bx>>5.
// Block 256 thr / 8 warps: warp -> (klgrp = w>>1) 16 kl x (mgrp = w&1) 32 m.
// Stage Ci (bf16, exact) + x split hi/lo bf16; 16 k-steps of mma over 256 ij;
// hi and lo both accumulate into the same fp32 fragments.
// ---------------------------------------------------------------------------
__global__ void __launch_bounds__(256) route_kernel(const float* __restrict__ Ci,
                                                    const float* __restrict__ x)
{
    extern __shared__ unsigned char sm[];
    const uint32_t sbase = (uint32_t)__cvta_generic_to_shared(sm);

    const int bx    = blockIdx.x;
    const int klt   = bx & 31;
    const int chunk = bx >> 5;
    const int t     = threadIdx.x;
    const int kl0   = klt * 64;
    const int ij0   = chunk * IJB;

    // --- Stage Ci tile: 256 ij x 64 kl fp32 -> bf16 swizzled ---
    #pragma unroll 4
    for (int p = 0; p < 16; p++) {
        int f = p * 256 + t;
        int r = f >> 4, c4 = f & 15;              // c4: 4-kl group
        float4 v = *reinterpret_cast<const float4*>(
            Ci + (size_t)(ij0 + r) * N_KL + kl0 + c4 * 4);
        __nv_bfloat162 h01 = __floats2bfloat162_rn(v.x, v.y);
        __nv_bfloat162 h23 = __floats2bfloat162_rn(v.z, v.w);
        uint2 u = make_uint2(*reinterpret_cast<unsigned*>(&h01),
                             *reinterpret_cast<unsigned*>(&h23));
        uint32_t off = swz((uint32_t)(r * 128 + c4 * 8));
        *reinterpret_cast<uint2*>(sm + SM_A + off) = u;
    }
    // --- Stage x tile: 256 ij x 64 m fp32 -> hi/lo bf16 swizzled ---
    #pragma unroll 4
    for (int p = 0; p < 16; p++) {
        int f = p * 256 + t;
        int r = f >> 4, m4 = f & 15;
        float4 v = *reinterpret_cast<const float4*>(
            x + (size_t)(ij0 + r) * N_M + m4 * 4);
        __nv_bfloat162 h01 = __floats2bfloat162_rn(v.x, v.y);
        __nv_bfloat162 h23 = __floats2bfloat162_rn(v.z, v.w);
        float2 f01 = __bfloat1622float2(h01);
        float2 f23 = __bfloat1622float2(h23);
        __nv_bfloat162 l01 = __floats2bfloat162_rn(v.x - f01.x, v.y - f01.y);
        __nv_bfloat162 l23 = __floats2bfloat162_rn(v.z - f23.x, v.w - f23.y);
        uint32_t off = swz((uint32_t)(r * 128 + m4 * 8));
        *reinterpret_cast<uint2*>(sm + SM_XH + off) =
            make_uint2(*reinterpret_cast<unsigned*>(&h01), *reinterpret_cast<unsigned*>(&h23));
        *reinterpret_cast<uint2*>(sm + SM_XL + off) =
            make_uint2(*reinterpret_cast<unsigned*>(&l01), *reinterpret_cast<unsigned*>(&l23));
    }
    __syncthreads();

    const int w     = t >> 5;
    const int lane  = t & 31;
    const int klgrp = w >> 1;     // 0..3 -> kl sub-block of 16
    const int mgrp  = w & 1;      // 0..1 -> m base 0/32

    // ldmatrix lane-address components (within a 16-ij k-step block)
    // A (want regs: a0=(kl0-7,ij0-7) a1=(kl8-15,ij0-7) a2=(kl0-7,ij8-15) a3=(kl8-15,ij8-15))
    const int aRow  = (lane & 7) + ((lane >> 4) & 1) * 8;
    const int aColB = klgrp * 32 + ((lane >> 3) & 1) * 16;
    // B x4 (2 n-tiles): b0=(k0-7,n0-7) b1=(k8-15,n0-7) b2=(k0-7,n8-15) b3=(k8-15,n8-15)
    const int bRow  = (lane & 7) + ((lane >> 3) & 1) * 8;
    const int bCol0 = mgrp * 64 + ((lane >> 4) & 1) * 16;  // n-tiles 0,1
    const int bCol1 = bCol0 + 32;                           // n-tiles 2,3

    float c[4][4];
    #pragma unroll
    for (int nt = 0; nt < 4; nt++)
        #pragma unroll
        for (int e = 0; e < 4; e++) c[nt][e] = 0.f;

    #pragma unroll 4
    for (int s = 0; s < 16; s++) {
        const uint32_t rowA = (uint32_t)((s * 16 + aRow) * 128 + aColB);
        const uint32_t rowB = (uint32_t)((s * 16 + bRow) * 128);

        uint32_t a0, a1, a2, a3;
        ldsm4t(a0, a1, a2, a3, sbase + SM_A + swz(rowA));

        uint32_t h0, h1, h2, h3, h4, h5, h6, h7;
        ldsm4t(h0, h1, h2, h3, sbase + SM_XH + swz(rowB + bCol0));
        ldsm4t(h4, h5, h6, h7, sbase + SM_XH + swz(rowB + bCol1));
        uint32_t l0, l1, l2, l3, l4, l5, l6, l7;
        ldsm4t(l0, l1, l2, l3, sbase + SM_XL + swz(rowB + bCol0));
        ldsm4t(l4, l5, l6, l7, sbase + SM_XL + swz(rowB + bCol1));

        mma16816(c[0], a0, a1, a2, a3, h0, h1);
        mma16816(c[1], a0, a1, a2, a3, h2, h3);
        mma16816(c[2], a0, a1, a2, a3, h4, h5);
        mma16816(c[3], a0, a1, a2, a3, h6, h7);
        mma16816(c[0], a0, a1, a2, a3, l0, l1);
        mma16816(c[1], a0, a1, a2, a3, l2, l3);
        mma16816(c[2], a0, a1, a2, a3, l4, l5);
        mma16816(c[3], a0, a1, a2, a3, l6, l7);
    }

    // Epilogue: c-fragment (m16n8): lane g=lane>>2 rows {g, g+8}, cols {2tt, 2tt+1}
    const int g  = lane >> 2;
    const int tt = lane & 3;
    float* dst = g_part + (size_t)chunk * XR_N;
    const int klA = kl0 + klgrp * 16 + g;
    #pragma unroll
    for (int nt = 0; nt < 4; nt++) {
        const int m = mgrp * 32 + nt * 8 + tt * 2;
        *reinterpret_cast<float2*>(&dst[(size_t)klA * N_M + m])       = make_float2(c[nt][0], c[nt][1]);
        *reinterpret_cast<float2*>(&dst[(size_t)(klA + 8) * N_M + m]) = make_float2(c[nt][2], c[nt][3]);
    }
}

// ---------------------------------------------------------------------------
// Kernel 2: fold 8 partials -> xr (~4.5 MB L2 traffic)
// ---------------------------------------------------------------------------
__global__ void __launch_bounds__(256) reduce_kernel()
{
    int t = blockIdx.x * 256 + threadIdx.x;
    float s0 = 0.f, s1 = 0.f;
    #pragma unroll
    for (int g = 0; g < NCHUNK; g += 2) {
        s0 += g_part[(size_t)g * XR_N + t];
        s1 += g_part[(size_t)(g + 1) * XR_N + t];
    }
    g_xr[t] = s0 + s1;
}

// ---------------------------------------------------------------------------
// Kernel 3: per-capsule transform (unchanged, proven). grid = 4096.
// ---------------------------------------------------------------------------
__global__ void __launch_bounds__(256) transform_kernel(const float* __restrict__ Wi,
                                                        float* __restrict__ y)
{
    __shared__ float sxr[256];
    __shared__ float part[32 * 33];

    const int bx   = blockIdx.x;
    const int b    = bx >> 1;
    const int half = bx & 1;
    const int i    = b >> 2;
    const int t    = threadIdx.x;
    const int w    = t >> 5;
    const int L    = t & 31;
    const int ka   = L >> 4;
    const int mi   = L & 15;

    const float4* W4 = reinterpret_cast<const float4*>(Wi + (size_t)b * 16384);
    const int l_base = half * 32 + w * 4;

    float4 wv[4][2];
    #pragma unroll
    for (int qq = 0; qq < 4; qq++) {
        const int l = l_base + qq;
        wv[qq][0] = __ldcs(&W4[ka * 1024 + l * 16 + mi]);
        wv[qq][1] = __ldcs(&W4[(ka + 2) * 1024 + l * 16 + mi]);
    }

    sxr[t] = g_xr[i * 256 + t];
    __syncthreads();

    const float4* sxr4 = reinterpret_cast<const float4*>(sxr);
    const float4 xv0 = sxr4[ka * 16 + mi];
    const float4 xv1 = sxr4[(ka + 2) * 16 + mi];

    #pragma unroll
    for (int qq = 0; qq < 4; qq++) {
        float4 a = wv[qq][0];
        float4 cc = wv[qq][1];
        float acc;
        acc = a.x * xv0.x;
        acc = fmaf(a.y, xv0.y, acc);
        acc = fmaf(a.z, xv0.z, acc);
        acc = fmaf(a.w, xv0.w, acc);
        acc = fmaf(cc.x, xv1.x, acc);
        acc = fmaf(cc.y, xv1.y, acc);
        acc = fmaf(cc.z, xv1.z, acc);
        acc = fmaf(cc.w, xv1.w, acc);
        part[(w * 4 + qq) * 33 + L] = acc;
    }
    __syncthreads();

    if (t < 32) {
        float s = 0.f;
        #pragma unroll
        for (int j = 0; j < 32; j++)
            s += part[t * 33 + j];
        y[b * 64 + half * 32 + t] = s;
    }
}

// ---------------------------------------------------------------------------
extern "C" void kernel_launch(void* const* d_in, const int* in_sizes, int n_in,
                              void* d_out, int out_size)
{
    const float* x  = nullptr;
    const float* Ci = nullptr;
    const float* Wi = nullptr;
    for (int i = 0; i < n_in; i++) {
        if (in_sizes[i] == 131072)        x  = (const float*)d_in[i];
        else if (in_sizes[i] == 4194304)  Ci = (const float*)d_in[i];
        else if (in_sizes[i] == 33554432) Wi = (const float*)d_in[i];
    }
    float* y = (float*)d_out;

    static bool attr_set = false;
    if (!attr_set) {
        cudaFuncSetAttribute(route_kernel,
                             cudaFuncAttributeMaxDynamicSharedMemorySize,
                             SMEM_ROUTE);
        attr_set = true;
    }

    route_kernel<<<NKLT * NCHUNK, 256, SMEM_ROUTE>>>(Ci, x);
    reduce_kernel<<<XR_N / 256, 256>>>();
    transform_kernel<<<4096, 256>>>(Wi, y);
}